// round 17
// baseline (speedup 1.0000x reference)
#include <cuda_runtime.h>
#include <cuda_bf16.h>
#include <cstdint>

#define DIM      256
#define TWO_DIM  512
#define KMAX     64
#define B_MAX    16384
#define NMT      (B_MAX / 16)
#define NKT      (DIM / 16)
#define NNT      (TWO_DIM / 8)

// ---------------- scratch (__device__ globals: allocation-guard-safe) ----------
__device__ __align__(16) uint32_t g_Afh[NMT * NKT * 32 * 4];
__device__ __align__(16) uint32_t g_Afl[NMT * NKT * 32 * 4];
__device__ __align__(16) uint32_t g_Wfh[NNT * NKT * 32 * 2];
__device__ __align__(16) uint32_t g_Wfl[NNT * NKT * 32 * 2];
__device__ __align__(128) float   g_H [B_MAX * TWO_DIM];
__device__ __align__(128) float   g_NS[B_MAX * DIM];       // raw neighbor sums

// ---------------- helpers ------------------------------------------------------
__device__ __forceinline__ uint32_t pack_bf16x2(float x0, float x1) {
    __nv_bfloat162 h = __floats2bfloat162_rn(x0, x1);
    return *reinterpret_cast<uint32_t*>(&h);
}
__device__ __forceinline__ void mma_bf16(float (&c)[4], const uint32_t* a,
                                         const uint32_t* b) {
    asm volatile("mma.sync.aligned.m16n8k16.row.col.f32.bf16.bf16.f32 "
                 "{%0,%1,%2,%3}, {%4,%5,%6,%7}, {%8,%9}, {%0,%1,%2,%3};"
                 : "+f"(c[0]), "+f"(c[1]), "+f"(c[2]), "+f"(c[3])
                 : "r"(a[0]), "r"(a[1]), "r"(a[2]), "r"(a[3]), "r"(b[0]), "r"(b[1]));
}
__device__ __forceinline__ uint32_t smem_u32(const void* p) {
    uint32_t a;
    asm("{ .reg .u64 t; cvta.to.shared.u64 t, %1; cvt.u32.u64 %0, t; }" : "=r"(a) : "l"(p));
    return a;
}
#define CPA16(dst, src) \
    asm volatile("cp.async.cg.shared.global [%0], [%1], 16;" :: "r"(dst), "l"(src))
#define CPA_COMMIT() asm volatile("cp.async.commit_group;" ::: "memory")
#define CPA_WAIT(n)  asm volatile("cp.async.wait_group %0;" :: "n"(n) : "memory")

// ---------------- Kernel 1: fused conv (W frags + A frags) ---------------------
__global__ __launch_bounds__(256)
void conv_all(const float* __restrict__ W,
              const int* __restrict__ nodes_v, const float* __restrict__ v2e,
              int B, int nmt)
{
    if ((int)blockIdx.x >= nmt) {
        const int blk = blockIdx.x - nmt;          // 0..127
        const int l   = threadIdx.x & 31;
        const int wid = threadIdx.x >> 5;
        const int nt  = blk >> 1;
        const int kt  = ((blk & 1) << 3) + wid;
        const int n   = nt * 8 + (l >> 2);
        uint2 hi, lo;
        #pragma unroll
        for (int r = 0; r < 2; r++) {
            const int k = kt * 16 + ((l & 3) << 1) + (r << 3);
            const float x0 = W[(size_t)k * TWO_DIM + n];
            const float x1 = W[(size_t)(k + 1) * TWO_DIM + n];
            const float h0 = __bfloat162float(__float2bfloat16_rn(x0));
            const float h1 = __bfloat162float(__float2bfloat16_rn(x1));
            (&hi.x)[r] = pack_bf16x2(x0, x1);
            (&lo.x)[r] = pack_bf16x2(x0 - h0, x1 - h1);
        }
        const size_t idx = ((size_t)nt * NKT + kt) * 32 + l;
        reinterpret_cast<uint2*>(g_Wfh)[idx] = hi;
        reinterpret_cast<uint2*>(g_Wfl)[idx] = lo;
        return;
    }
    const int mt  = blockIdx.x;
    const int l   = threadIdx.x & 31;
    const int wid = threadIdx.x >> 5;
    const int row0 = (l >> 2);
    int b0 = mt * 16 + row0;     if (b0 >= B) b0 = B - 1;
    int b1 = mt * 16 + row0 + 8; if (b1 >= B) b1 = B - 1;
    const size_t v0 = (size_t)nodes_v[b0] * DIM;
    const size_t v1 = (size_t)nodes_v[b1] * DIM;
    #pragma unroll 1
    for (int kt = wid; kt < NKT; kt += 8) {
        uint4 hi, lo;
        #pragma unroll
        for (int r = 0; r < 4; r++) {
            const int col = kt * 16 + ((l & 3) << 1) + ((r & 2) << 2);
            const size_t base = (r & 1) ? v1 : v0;
            const float x0 = v2e[base + col];
            const float x1 = v2e[base + col + 1];
            const float h0 = __bfloat162float(__float2bfloat16_rn(x0));
            const float h1 = __bfloat162float(__float2bfloat16_rn(x1));
            (&hi.x)[r] = pack_bf16x2(x0, x1);
            (&lo.x)[r] = pack_bf16x2(x0 - h0, x1 - h1);
        }
        const size_t idx = ((size_t)mt * NKT + kt) * 32 + l;
        reinterpret_cast<uint4*>(g_Afh)[idx] = hi;
        reinterpret_cast<uint4*>(g_Afl)[idx] = lo;
    }
}

// ---------------- Kernel 2: FUSED gemm + gather, 4:1 interleaved ---------------
#define RPB 4
#define CHK 8
#define CSMEM (2 * RPB * CHK * 64 * 16)    // 64 KB (gather branch only)

__global__ __launch_bounds__(256, 3)
void mid_fused(const int* __restrict__ neighbors,
               const int* __restrict__ neighbor_counts,
               const float* __restrict__ u2e,
               int B, int ngather, int ngemm)
{
    extern __shared__ uint4 sbuf[];
    const int t  = threadIdx.x;
    const int m5 = (int)(blockIdx.x % 5u);

    if (m5 == 4) {
        // ================= GEMM tile (CTA 128m x 64n, warp 32m x 32n) =========
        const int blk = (int)(blockIdx.x / 5u);
        if (blk >= ngemm) return;
        const int bm  = blk >> 3;           // m-block (128 rows)
        const int bn  = blk & 7;            // n-block (64 cols)
        const int wid = t >> 5;
        const int lid = t & 31;
        const int wm  = wid & 3;            // 4 m-slices of 32
        const int wn  = wid >> 2;           // 2 n-slices of 32
        const int m0t = bm * 8;
        const int n0t = bn * 8;

        float acc[2][4][4];
        #pragma unroll
        for (int mf = 0; mf < 2; mf++)
            #pragma unroll
            for (int nf = 0; nf < 4; nf++)
                #pragma unroll
                for (int q = 0; q < 4; q++) acc[mf][nf][q] = 0.f;

        const uint4* Afh4 = reinterpret_cast<const uint4*>(g_Afh);
        const uint4* Afl4 = reinterpret_cast<const uint4*>(g_Afl);
        const uint2* Wfh2 = reinterpret_cast<const uint2*>(g_Wfh);
        const uint2* Wfl2 = reinterpret_cast<const uint2*>(g_Wfl);

        #pragma unroll 2
        for (int kt = 0; kt < NKT; kt++) {
            uint4 ah[2], al[2];
            #pragma unroll
            for (int mf = 0; mf < 2; mf++) {
                const size_t ai = ((size_t)(m0t + wm * 2 + mf) * NKT + kt) * 32 + lid;
                ah[mf] = Afh4[ai];
                al[mf] = Afl4[ai];
            }
            #pragma unroll
            for (int nf = 0; nf < 4; nf++) {
                const size_t bi = ((size_t)(n0t + wn * 4 + nf) * NKT + kt) * 32 + lid;
                const uint2 bh = Wfh2[bi];
                const uint2 bl = Wfl2[bi];
                #pragma unroll
                for (int mf = 0; mf < 2; mf++) {
                    mma_bf16(acc[mf][nf], &ah[mf].x, &bh.x);
                    mma_bf16(acc[mf][nf], &ah[mf].x, &bl.x);
                    mma_bf16(acc[mf][nf], &al[mf].x, &bh.x);
                }
            }
        }

        const int rbase = bm * 128 + wm * 32 + (lid >> 2);
        const int cbase = bn * 64 + wn * 32 + (lid & 3) * 2;
        #pragma unroll
        for (int mf = 0; mf < 2; mf++) {
            #pragma unroll
            for (int nf = 0; nf < 4; nf++) {
                const int row = rbase + mf * 16;
                const int col = cbase + nf * 8;
                if (row < B)
                    *reinterpret_cast<float2*>(&g_H[(size_t)row * TWO_DIM + col]) =
                        make_float2(acc[mf][nf][0], acc[mf][nf][1]);
                if (row + 8 < B)
                    *reinterpret_cast<float2*>(&g_H[(size_t)(row + 8) * TWO_DIM + col]) =
                        make_float2(acc[mf][nf][2], acc[mf][nf][3]);
            }
        }
        return;
    }

    // ================= neighbor-sum gather (round-14 passing code) =============
    __shared__ int snb[RPB][KMAX];
    __shared__ int scnt[RPB];

    const int gblk = (int)(blockIdx.x / 5u) * 4 + m5;
    if (gblk >= ngather) return;
    const int gi   = t >> 6;
    const int gt   = t & 63;
    const int c4   = gt * 4;
    const int row0 = gblk * RPB;

    if (t < RPB * KMAX) {
        int r = t >> 6, k = t & 63;
        int b = row0 + r; if (b >= B) b = B - 1;
        snb[r][k] = neighbors[(size_t)b * KMAX + k];
    }
    if (t < RPB) {
        int b = row0 + t; if (b >= B) b = B - 1;
        scnt[t] = neighbor_counts[b];
    }
    __syncthreads();

    const int r   = gi;
    const int cnt = scnt[r];
    int brow = row0 + r; if (brow >= B) brow = B - 1;

    if (cnt > 0) {
        const int* nb = snb[r];
        const uint32_t sb0 = smem_u32(sbuf) + (uint32_t)(((r * CHK) * 64 + gt) * 16);
        const uint32_t bufstride = (uint32_t)(RPB * CHK * 64 * 16);
        const int nfull = cnt >> 3;

        float4 a0 = make_float4(0, 0, 0, 0), a1 = a0;

        if (nfull > 0) {
            #pragma unroll
            for (int j = 0; j < CHK; j++)
                CPA16(sb0 + j * 64 * 16, &u2e[(size_t)nb[j] * DIM + c4]);
            CPA_COMMIT();
            #pragma unroll 1
            for (int c = 1; c < nfull; c++) {
                const uint32_t dsty = sb0 + (c & 1) * bufstride;
                const int* nbc = nb + c * CHK;
                #pragma unroll
                for (int j = 0; j < CHK; j++)
                    CPA16(dsty + j * 64 * 16, &u2e[(size_t)nbc[j] * DIM + c4]);
                CPA_COMMIT();
                CPA_WAIT(1);
                const uint4* src = reinterpret_cast<const uint4*>(
                    sbuf + ((size_t)((c - 1) & 1) * RPB * CHK * 64) + (size_t)r * CHK * 64 + gt);
                #pragma unroll
                for (int j = 0; j < CHK; j += 2) {
                    float4 x0 = *reinterpret_cast<const float4*>(&src[j * 64]);
                    float4 x1 = *reinterpret_cast<const float4*>(&src[(j + 1) * 64]);
                    a0.x += x0.x; a0.y += x0.y; a0.z += x0.z; a0.w += x0.w;
                    a1.x += x1.x; a1.y += x1.y; a1.z += x1.z; a1.w += x1.w;
                }
            }
            CPA_WAIT(0);
            const uint4* src = reinterpret_cast<const uint4*>(
                sbuf + ((size_t)((nfull - 1) & 1) * RPB * CHK * 64) + (size_t)r * CHK * 64 + gt);
            #pragma unroll
            for (int j = 0; j < CHK; j += 2) {
                float4 x0 = *reinterpret_cast<const float4*>(&src[j * 64]);
                float4 x1 = *reinterpret_cast<const float4*>(&src[(j + 1) * 64]);
                a0.x += x0.x; a0.y += x0.y; a0.z += x0.z; a0.w += x0.w;
                a1.x += x1.x; a1.y += x1.y; a1.z += x1.z; a1.w += x1.w;
            }
        }
        #pragma unroll 1
        for (int k = nfull * CHK; k < cnt; k++) {
            float4 x = *reinterpret_cast<const float4*>(&u2e[(size_t)nb[k] * DIM + c4]);
            a0.x += x.x; a0.y += x.y; a0.z += x.z; a0.w += x.w;
        }
        float4 ns;
        ns.x = a0.x + a1.x; ns.y = a0.y + a1.y;
        ns.z = a0.z + a1.z; ns.w = a0.w + a1.w;
        *reinterpret_cast<float4*>(&g_NS[(size_t)brow * DIM + c4]) = ns;
    }
}

// ---------------- Kernel 3: final combine (pure streaming) ---------------------
__global__ __launch_bounds__(256)
void fin(const int* __restrict__ nodes_u,
         const int* __restrict__ nodes_v,
         const int* __restrict__ neighbor_counts,
         const float* __restrict__ u2e,
         const float* __restrict__ v2e,
         const float* __restrict__ bvec,
         float* __restrict__ out,
         int B)
{
    __shared__ float sred[RPB][2];
    const int t    = threadIdx.x;
    const int gi   = t >> 6;
    const int gt   = t & 63;
    const int c4   = gt * 4;
    const int row0 = blockIdx.x * RPB;

    int b = row0 + gi; if (b >= B) b = B - 1;
    const int cnt = neighbor_counts[b];
    const int ui  = nodes_u[b];
    const int vi  = nodes_v[b];

    const float4 self4 = *reinterpret_cast<const float4*>(&u2e[(size_t)ui * DIM + c4]);
    const float4 v4    = *reinterpret_cast<const float4*>(&v2e[(size_t)vi * DIM + c4]);
    float partial;
    if (cnt > 0) {
        const size_t hb = (size_t)b * TWO_DIM;
        const float4 h1 = *reinterpret_cast<const float4*>(&g_H[hb + c4]);
        const float4 h2 = *reinterpret_cast<const float4*>(&g_H[hb + DIM + c4]);
        const float4 ns = *reinterpret_cast<const float4*>(&g_NS[(size_t)b * DIM + c4]);
        const float4 b4 = *reinterpret_cast<const float4*>(&bvec[c4]);
        const float inv = 1.f / (float)cnt;
        partial = self4.x * h1.x + self4.y * h1.y + self4.z * h1.z + self4.w * h1.w
                + (ns.x * inv) * h2.x + (ns.y * inv) * h2.y
                + (ns.z * inv) * h2.z + (ns.w * inv) * h2.w
                + b4.x * v4.x + b4.y * v4.y + b4.z * v4.z + b4.w * v4.w;
    } else {
        partial = self4.x * v4.x + self4.y * v4.y + self4.z * v4.z + self4.w * v4.w;
    }
    #pragma unroll
    for (int o = 16; o; o >>= 1)
        partial += __shfl_down_sync(0xffffffffu, partial, o);
    if ((t & 31) == 0) sred[gi][(t >> 5) & 1] = partial;
    __syncthreads();

    if (t < RPB) {
        float s = sred[t][0] + sred[t][1];
        if (row0 + t < B) out[row0 + t] = s;
    }
}

// ---------------- launch --------------------------------------------------------
extern "C" void kernel_launch(void* const* d_in, const int* in_sizes, int n_in,
                              void* d_out, int out_size)
{
    const int*   nodes_u         = (const int*)  d_in[0];
    const int*   nodes_v         = (const int*)  d_in[1];
    const int*   neighbors       = (const int*)  d_in[2];
    const int*   neighbor_counts = (const int*)  d_in[3];
    const float* u2e             = (const float*)d_in[4];
    const float* v2e             = (const float*)d_in[5];
    const float* W               = (const float*)d_in[6];
    const float* bvec            = (const float*)d_in[7];
    float*       out             = (float*)d_out;

    int B = in_sizes[0];
    if (B > B_MAX) B = B_MAX;
    const int nmt     = (B + 15) / 16;
    const int ngather = (B + RPB - 1) / RPB;
    const int ngemm   = ((B + 127) / 128) * 8;
    // 4:1 interleave: grid of 5-block groups (4 gather + 1 gemm)
    int grp = (ngather + 3) / 4;
    if (ngemm > grp) grp = ngemm;
    const int grid5 = grp * 5;

    cudaFuncSetAttribute(mid_fused, cudaFuncAttributeMaxDynamicSharedMemorySize, CSMEM);

    conv_all<<<nmt + 128, 256>>>(W, nodes_v, v2e, B, nmt);
    mid_fused<<<grid5, 256, CSMEM>>>(neighbors, neighbor_counts, u2e, B, ngather, ngemm);
    fin<<<ngather, 256>>>(nodes_u, nodes_v, neighbor_counts, u2e, v2e, bvec, out, B);
}